// round 5
// baseline (speedup 1.0000x reference)
#include <cuda_runtime.h>
#include <cstdint>
#include <math.h>

// ---------------- problem constants ----------------
#define BB 8
#define IC1 4
#define OC1 8
#define OC2 10
#define LTOT 131072          // 128*128*8 grid points
#define NUMEL 62720          // 10*28*28*8

// output regions (flat f32 concat: X_t, grid, reg, moved)
#define XT_OFF   0
#define XT_SIZE  (8*4*131072)            // 4194304
#define GRID_OFF XT_SIZE
#define GRID_SIZE (8*131072*3)           // 3145728
#define REG_OFF  (GRID_OFF + GRID_SIZE)  // 7340032
#define MOVED_OFF (REG_OFF + 8)          // 7340040

typedef unsigned long long ull;

// ---------------- scratch (no allocs allowed) ----------------
__device__ float s_h1[8*8*61*488];    // (b,oc,od,oh,w) = 1,905,664 floats
__device__ float s_feat[8*NUMEL];     // conv2 output, reshape layout
__device__ float s_part[32*8*8];      // fc1 partials [o][ks][b]
__device__ float s_RT[8*8*12];        // per (b,t): R row-major [9], T [3]
__device__ int   s_ctr;               // last-block counter (self-resetting)

// ---------------- f32x2 helpers ----------------
__device__ __forceinline__ ull ffma2(ull a, ull b, ull c) {
    ull d;
    asm("fma.rn.f32x2 %0, %1, %2, %3;" : "=l"(d) : "l"(a), "l"(b), "l"(c));
    return d;
}
__device__ __forceinline__ ull pack2(float v) {
    ull d;
    asm("mov.b64 %0, {%1, %1};" : "=l"(d) : "f"(v));
    return d;
}
__device__ __forceinline__ float2 unpack2(ull v) {
    float2 r;
    asm("mov.b64 {%0, %1}, %2;" : "=f"(r.x), "=f"(r.y) : "l"(v));
    return r;
}

// =========================================================================
// conv1 (7,7,1) + maxpool(2,2,1) + relu
// block = (od, b), 512 threads: ocg = tid>>8 handles oc 4*ocg..4*ocg+3,
// r = tid&255 -> (oh 0..60, wpair 0..3), 244 active per group.
// acc[4][4] (32 regs) + rows[2][8] (32) + 2 ulonglong2 (8) => no spill.
// padded smem rows (80B stride) -> conflict-free LDS.64.
// =========================================================================
__global__ void __launch_bounds__(512)
conv1_kernel(const float* __restrict__ x, const float* __restrict__ wt,
             const float* __restrict__ bias)
{
    __shared__ ull sxu[1024*5];            // [row(1024)][5] ull, row = dd*128+h
    __shared__ ull swu[49*8];              // current ic: [kk*8 + oc] = pack2(w)
    const int od = blockIdx.x, b = blockIdx.y;
    const int tid = threadIdx.x;
    const int ocg = tid >> 8;              // 0 or 1
    const int r   = tid & 255;

    ull acc[4][4];
    #pragma unroll
    for (int oc = 0; oc < 4; oc++)
        #pragma unroll
        for (int p = 0; p < 4; p++) acc[oc][p] = 0ull;

    const int oh = r >> 2;
    const int wp = r & 3;
    const bool act = (r < 244);
    const int hb = 2 * oh;

    for (int ic = 0; ic < IC1; ic++) {
        __syncthreads();
        // stage this ic's weights: wt[oc*196 + ic*49 + kk]
        for (int i = tid; i < 49*8; i += 512) {
            int oc = i / 49, kk = i % 49;
            swu[kk*8 + oc] = pack2(wt[oc*(IC1*49) + ic*49 + kk]);
        }
        // copy 8192 floats (rows d=2od..2od+7, h 0..127, w 0..7) with padding
        const float4* src = (const float4*)(x + ((size_t)(b*IC1 + ic))*131072 + (size_t)od*2048);
        for (int i = tid; i < 2048; i += 512) {
            float4 v = src[i];
            int row = i >> 1;
            int q2  = (i & 1) * 2;
            ull* d = sxu + row*5 + q2;
            d[0] = ((const ull*)&v)[0];
            d[1] = ((const ull*)&v)[1];
        }
        __syncthreads();
        if (act) {
            ull rows[2][8];
            #pragma unroll
            for (int j = 0; j < 8; j++)
                rows[0][j] = sxu[(hb + j)*5 + wp];
            #pragma unroll
            for (int kd = 0; kd < 7; kd++) {
                const int lo = kd & 1, hi = lo ^ 1;
                #pragma unroll
                for (int j = 0; j < 8; j++)
                    rows[hi][j] = sxu[((kd + 1)*128 + hb + j)*5 + wp];
                #pragma unroll
                for (int kh = 0; kh < 7; kh++) {
                    const ulonglong2* wrow = (const ulonglong2*)(swu + (kd*7 + kh)*8 + ocg*4);
                    ulonglong2 w0 = wrow[0], w1 = wrow[1];
                    #pragma unroll
                    for (int ph = 0; ph < 2; ph++) {
                        ull xl = rows[lo][kh + ph];
                        ull xh = rows[hi][kh + ph];
                        acc[0][ph]   = ffma2(xl, w0.x, acc[0][ph]);
                        acc[0][2+ph] = ffma2(xh, w0.x, acc[0][2+ph]);
                        acc[1][ph]   = ffma2(xl, w0.y, acc[1][ph]);
                        acc[1][2+ph] = ffma2(xh, w0.y, acc[1][2+ph]);
                        acc[2][ph]   = ffma2(xl, w1.x, acc[2][ph]);
                        acc[2][2+ph] = ffma2(xh, w1.x, acc[2][2+ph]);
                        acc[3][ph]   = ffma2(xl, w1.y, acc[3][ph]);
                        acc[3][2+ph] = ffma2(xh, w1.y, acc[3][2+ph]);
                    }
                }
            }
        }
    }

    if (act) {
        #pragma unroll
        for (int oc = 0; oc < 4; oc++) {
            const int ocG = ocg*4 + oc;
            float2 v0 = unpack2(acc[oc][0]);
            float2 v1 = unpack2(acc[oc][1]);
            float2 v2 = unpack2(acc[oc][2]);
            float2 v3 = unpack2(acc[oc][3]);
            float bv = bias[ocG];
            float mx = fmaxf(fmaxf(fmaxf(v0.x, v1.x), fmaxf(v2.x, v3.x)) + bv, 0.f);
            float my = fmaxf(fmaxf(fmaxf(v0.y, v1.y), fmaxf(v2.y, v3.y)) + bv, 0.f);
            size_t idx = ((size_t)(b*8 + ocG)*61 + od)*488 + oh*8 + wp*2;
            *(float2*)(s_h1 + idx) = make_float2(mx, my);
        }
    }
}

// =========================================================================
// conv2 (5,5,1) + maxpool + relu -> s_feat
// grid (28 oi, 8 b, 2 ojhalf), 128 threads: ocg = tid>>6 handles 5 ocs,
// r = tid&63 -> (ojr 0..13, wp), 56 active per group.
// acc[5][4] (40 regs) + rows[2][6] (24) + 5 ull (10) => no spill.
// =========================================================================
__global__ void __launch_bounds__(128, 4)
conv2_kernel(const float* __restrict__ wt, const float* __restrict__ bias)
{
    __shared__ ull stu[6*32*5];            // [(dd*32+hh)*5 + q]
    __shared__ ull swu[OC1*25*10];         // [(ic*25+kk)*10 + oc]
    const int oi = blockIdx.x, b = blockIdx.y, ojh = blockIdx.z;
    const int tid = threadIdx.x;
    const int ocg = tid >> 6;              // 0 or 1
    const int r   = tid & 63;
    const int h0 = 28 * ojh;

    for (int i = tid; i < OC2*OC1*25; i += 128) {
        int oc = i / (OC1*25);
        int rr = i % (OC1*25);
        int ic = rr / 25;
        int kk = rr % 25;
        swu[(ic*25 + kk)*10 + oc] = pack2(wt[i]);
    }

    ull acc[5][4];
    #pragma unroll
    for (int oc = 0; oc < 5; oc++)
        #pragma unroll
        for (int p = 0; p < 4; p++) acc[oc][p] = 0ull;

    const int ojr = r >> 2;
    const int wp  = r & 3;
    const bool act = (r < 56);
    const int hbl = 2 * ojr;

    const ull* h1u = (const ull*)s_h1;

    for (int ic = 0; ic < OC1; ic++) {
        __syncthreads();
        const size_t rb = (size_t)(b*8 + ic)*14884;
        for (int j = tid; j < 768; j += 128) {
            int dd = j >> 7;
            int rj = j & 127;
            int hh = rj >> 2, q = rj & 3;
            stu[(dd*32 + hh)*5 + q] = h1u[rb + (size_t)(2*oi + dd)*244 + (size_t)(h0 + hh)*4 + q];
        }
        __syncthreads();
        if (act) {
            ull rows[2][6];
            #pragma unroll
            for (int j = 0; j < 6; j++)
                rows[0][j] = stu[(hbl + j)*5 + wp];
            #pragma unroll
            for (int kd = 0; kd < 5; kd++) {
                const int lo = kd & 1, hi = lo ^ 1;
                #pragma unroll
                for (int j = 0; j < 6; j++)
                    rows[hi][j] = stu[((kd + 1)*32 + hbl + j)*5 + wp];
                #pragma unroll
                for (int kh = 0; kh < 5; kh++) {
                    const ull* wrow = swu + (ic*25 + kd*5 + kh)*10 + ocg*5;
                    ull w0 = wrow[0], w1 = wrow[1], w2 = wrow[2], w3 = wrow[3], w4 = wrow[4];
                    #pragma unroll
                    for (int ph = 0; ph < 2; ph++) {
                        ull xl = rows[lo][kh + ph];
                        ull xh = rows[hi][kh + ph];
                        acc[0][ph]   = ffma2(xl, w0, acc[0][ph]);
                        acc[0][2+ph] = ffma2(xh, w0, acc[0][2+ph]);
                        acc[1][ph]   = ffma2(xl, w1, acc[1][ph]);
                        acc[1][2+ph] = ffma2(xh, w1, acc[1][2+ph]);
                        acc[2][ph]   = ffma2(xl, w2, acc[2][ph]);
                        acc[2][2+ph] = ffma2(xh, w2, acc[2][2+ph]);
                        acc[3][ph]   = ffma2(xl, w3, acc[3][ph]);
                        acc[3][2+ph] = ffma2(xh, w3, acc[3][2+ph]);
                        acc[4][ph]   = ffma2(xl, w4, acc[4][ph]);
                        acc[4][2+ph] = ffma2(xh, w4, acc[4][2+ph]);
                    }
                }
            }
        }
    }

    if (act) {
        const int oj = ojh*14 + ojr;
        #pragma unroll
        for (int oc = 0; oc < 5; oc++) {
            const int ocG = ocg*5 + oc;
            float2 v0 = unpack2(acc[oc][0]);
            float2 v1 = unpack2(acc[oc][1]);
            float2 v2 = unpack2(acc[oc][2]);
            float2 v3 = unpack2(acc[oc][3]);
            float bv = bias[ocG];
            float mx = fmaxf(fmaxf(fmaxf(v0.x, v1.x), fmaxf(v2.x, v3.x)) + bv, 0.f);
            float my = fmaxf(fmaxf(fmaxf(v0.y, v1.y), fmaxf(v2.y, v3.y)) + bv, 0.f);
            size_t idx = (size_t)b*NUMEL + ocG*6272 + oi*224 + oj*8 + wp*2;
            *(float2*)(s_feat + idx) = make_float2(mx, my);
        }
    }
}

// =========================================================================
// fc1 partials (float4) + LAST-BLOCK finalize (fc2 + tanh + rigid -> s_RT).
// grid (32 o, 8 ksplit), 256 threads.  counter self-resets for graph replay.
// =========================================================================
__global__ void __launch_bounds__(256)
fc1_kernel(const float* __restrict__ fw, const float* __restrict__ f1b,
           const float* __restrict__ f2w, const float* __restrict__ f2b)
{
    const int o = blockIdx.x, ks = blockIdx.y;
    const int tid = threadIdx.x;
    const int lane = tid & 31, wid = tid >> 5;
    __shared__ float red[8];
    const float4* wrow = (const float4*)(fw + (size_t)o*NUMEL + ks*7840);

    for (int b = 0; b < 8; b++) {
        const float4* frow = (const float4*)(s_feat + (size_t)b*NUMEL + ks*7840);
        float s = 0.f;
        for (int i = tid; i < 1960; i += 256) {
            float4 w = wrow[i], f = frow[i];
            s += w.x*f.x + w.y*f.y + w.z*f.z + w.w*f.w;
        }
        #pragma unroll
        for (int off = 16; off; off >>= 1) s += __shfl_xor_sync(0xffffffffu, s, off);
        if (lane == 0) red[wid] = s;
        __syncthreads();
        if (tid == 0) {
            float t = 0.f;
            #pragma unroll
            for (int w = 0; w < 8; w++) t += red[w];
            s_part[o*64 + ks*8 + b] = t;
        }
        __syncthreads();
    }

    // ---- last-block finalize ----
    __shared__ int is_last;
    __threadfence();
    if (tid == 0) {
        int v = atomicAdd(&s_ctr, 1);
        is_last = (v == 32*8 - 1);
    }
    __syncthreads();
    if (!is_last) return;
    __threadfence();

    __shared__ float sw[1536];
    __shared__ float sfch[256];
    __shared__ float sth[384];

    for (int i = tid; i < 1536; i += 256) sw[i] = f2w[i];
    {
        const int b = tid >> 5, oo = tid & 31;
        float v = 0.f;
        #pragma unroll
        for (int k = 0; k < 8; k++) v += s_part[oo*64 + k*8 + b];
        sfch[b*32 + oo] = fmaxf(v + f1b[oo], 0.f);
    }
    __syncthreads();

    for (int i = tid; i < 384; i += 256) {
        const int b = i / 48, rr = i % 48;
        float s = f2b[rr];
        const float* w = sw + rr*32;
        const float* f = sfch + b*32;
        #pragma unroll
        for (int j = 0; j < 32; j++) s += f[j] * w[j];
        sth[b*48 + rr] = tanhf(s);
    }
    __syncthreads();

    if (tid < 64) {
        const int b = tid >> 3, t = tid & 7;
        const float* th = sth + b*48 + t*6;
        const float PI = 3.14159274101257324f;
        float c0, s0, c1, s1, c2, s2;
        sincosf(PI*th[0], &s0, &c0);
        sincosf(PI*th[1], &s1, &c1);
        sincosf(PI*th[2], &s2, &c2);
        float R[3][3];
        R[0][0] = c0*c1;  R[0][1] = -s0*c2 + c0*s1*s2;  R[0][2] =  s0*s2 + c0*s1*c2;
        R[1][0] = s0*c1;  R[1][1] =  c0*c2 + s0*s1*s2;  R[1][2] = -c0*s2 + s0*s1*c2;
        R[2][0] = -s1;    R[2][1] =  c1*s2;             R[2][2] =  c1*c2;
        const float szv[3] = {128.f, 128.f, 8.f};
        const float cen[3] = {64.f, 64.f, 4.f};
        float* rr = s_RT + (b*8 + t)*12;
        #pragma unroll
        for (int m = 0; m < 3; m++)
            #pragma unroll
            for (int k = 0; k < 3; k++) rr[m*3 + k] = R[m][k];
        #pragma unroll
        for (int k = 0; k < 3; k++)
            rr[9 + k] = th[3 + k]*szv[k] + cen[k] - (cen[0]*R[0][k] + cen[1]*R[1][k] + cen[2]*R[2][k]);
    }
    if (tid == 0) s_ctr = 0;   // reset for next graph replay
}

// =========================================================================
// fused flow + grid write + trilinear grid_sample + (blocks 512..519) moved/reg
// =========================================================================
__global__ void __launch_bounds__(256)
flow_sample_kernel(const float* __restrict__ x,
                   const float* __restrict__ pos,
                   const float* __restrict__ centers,
                   float* __restrict__ out)
{
    __shared__ float rt[768];
    const int tid = threadIdx.x;
    for (int i = tid; i < 768; i += 256) rt[i] = s_RT[i];
    __syncthreads();

    const float tess[8][3] = {{32,32,4},{32,96,4},{96,32,4},{96,96,4},
                              {32,64,4},{96,64,4},{64,32,4},{64,96,4}};

    if (blockIdx.x < 512) {
        const int l = blockIdx.x * 256 + tid;
        const int gi = l >> 10, gj = (l >> 3) & 127, gk = l & 7;

        float wn[8], wsum = 0.f;
        #pragma unroll
        for (int t = 0; t < 8; t++) {
            float dx = gi - tess[t][0], dy = gj - tess[t][1], dz = gk - tess[t][2];
            float d = sqrtf(dx*dx + dy*dy + dz*dz);
            float wv = expf(-d * 0.1f);
            wn[t] = wv;
            wsum += wv;
        }
        const float inv = 1.f / wsum;
        const float fi = (float)gi, fj = (float)gj, fk = (float)gk;

        for (int b = 0; b < BB; b++) {
            float a0 = 0.f, a1 = 0.f;
            #pragma unroll
            for (int t = 0; t < 8; t++) {
                const float* r = rt + (b*8 + t)*12;
                float f0 = fi*r[0] + fj*r[3] + fk*r[6] + r[9];
                float f1 = fi*r[1] + fj*r[4] + fk*r[7] + r[10];
                a0 += wn[t]*f0;
                a1 += wn[t]*f1;
            }
            a0 *= inv; a1 *= inv;
            float nf0 = a0 * (1.f/64.f) - 1.f;
            float nf1 = a1 * (1.f/64.f) - 1.f;

            float* g = out + GRID_OFF + ((size_t)b*LTOT + l)*3;
            g[0] = 0.f; g[1] = nf1; g[2] = nf0;

            float iy = (nf1 + 1.f)*64.f - 0.5f;
            float iz = (nf0 + 1.f)*64.f - 0.5f;
            float z0 = floorf(iz), y0 = floorf(iy);
            float acc[4] = {0.f, 0.f, 0.f, 0.f};
            #pragma unroll
            for (int dz = 0; dz < 2; dz++) {
                float zc = z0 + dz;
                float wz = 1.f - fabsf(iz - zc);
                bool zv = (zc >= 0.f) && (zc < 128.f);
                int zi = (int)fminf(fmaxf(zc, 0.f), 127.f);
                #pragma unroll
                for (int dy = 0; dy < 2; dy++) {
                    float yc = y0 + dy;
                    float wy = 1.f - fabsf(iy - yc);
                    bool ok = zv && (yc >= 0.f) && (yc < 128.f);
                    int yi = (int)fminf(fmaxf(yc, 0.f), 127.f);
                    float wgt = ok ? wz*wy*0.5f : 0.f;
                    const float* p = x + ((size_t)b*4*128 + zi)*1024 + yi*8;
                    acc[0] += wgt*(p[3]           + p[4]);
                    acc[1] += wgt*(p[3 + 131072]  + p[4 + 131072]);
                    acc[2] += wgt*(p[3 + 262144]  + p[4 + 262144]);
                    acc[3] += wgt*(p[3 + 393216]  + p[4 + 393216]);
                }
            }
            #pragma unroll
            for (int c = 0; c < 4; c++)
                out[XT_OFF + (size_t)(b*4 + c)*LTOT + l] = acc[c];
        }
    } else {
        // moved + reg for batch b
        const int b = blockIdx.x - 512;
        __shared__ float red[256];
        float dist = 0.f;
        if (tid < 100) {
            float p0 = pos[(b*100 + tid)*3 + 0];
            float p1 = pos[(b*100 + tid)*3 + 1];
            float p2 = pos[(b*100 + tid)*3 + 2];
            int i0 = (int)fminf(fmaxf(rintf(p0), 0.f), 127.f);
            int i1 = (int)fminf(fmaxf(rintf(p1), 0.f), 127.f);
            int i2 = (int)fminf(fmaxf(rintf(p2), 0.f), 7.f);

            float wn[8], wsum = 0.f;
            #pragma unroll
            for (int t = 0; t < 8; t++) {
                float dx = i0 - tess[t][0], dy = i1 - tess[t][1], dz = i2 - tess[t][2];
                float d = sqrtf(dx*dx + dy*dy + dz*dz);
                float wv = expf(-d * 0.1f);
                wn[t] = wv;
                wsum += wv;
            }
            const float inv = 1.f / wsum;
            const float fi = (float)i0, fj = (float)i1, fk = (float)i2;
            float a0 = 0.f, a1 = 0.f;
            #pragma unroll
            for (int t = 0; t < 8; t++) {
                const float* r = rt + (b*8 + t)*12;
                float f0 = fi*r[0] + fj*r[3] + fk*r[6] + r[9];
                float f1 = fi*r[1] + fj*r[4] + fk*r[7] + r[10];
                a0 += wn[t]*f0;
                a1 += wn[t]*f1;
            }
            a0 *= inv; a1 *= inv;
            float nf0 = a0 * (1.f/64.f) - 1.f;
            float nf1 = a1 * (1.f/64.f) - 1.f;

            float m0 = 2.f*p0 - (0.5f + 0.5f*nf0)*127.f;
            float m1 = 2.f*p1 - (0.5f + 0.5f*nf1)*127.f;
            float m2 = 2.f*p2 - 3.5f;
            float* mo = out + MOVED_OFF + (size_t)(b*100 + tid)*3;
            mo[0] = m0; mo[1] = m1; mo[2] = m2;
            float c0 = centers[tid*3 + 0], c1 = centers[tid*3 + 1], c2 = centers[tid*3 + 2];
            dist = sqrtf((m0-c0)*(m0-c0) + (m1-c1)*(m1-c1) + (m2-c2)*(m2-c2));
        }
        red[tid] = dist;
        __syncthreads();
        for (int k = 128; k > 0; k >>= 1) {
            if (tid < k) red[tid] += red[tid + k];
            __syncthreads();
        }
        if (tid == 0) out[REG_OFF + b] = red[0] / 100.f;
    }
}

// =========================================================================
extern "C" void kernel_launch(void* const* d_in, const int* in_sizes, int n_in,
                              void* d_out, int out_size)
{
    const float* x       = (const float*)d_in[0];
    const float* pos     = (const float*)d_in[1];
    const float* centers = (const float*)d_in[2];
    const float* c1w     = (const float*)d_in[3];
    const float* c1b     = (const float*)d_in[4];
    const float* c2w     = (const float*)d_in[5];
    const float* c2b     = (const float*)d_in[6];
    const float* f1w     = (const float*)d_in[7];
    const float* f1b     = (const float*)d_in[8];
    const float* f2w     = (const float*)d_in[9];
    const float* f2b     = (const float*)d_in[10];
    float* out = (float*)d_out;

    conv1_kernel<<<dim3(61, 8), 512>>>(x, c1w, c1b);
    conv2_kernel<<<dim3(28, 8, 2), 128>>>(c2w, c2b);
    fc1_kernel<<<dim3(32, 8), 256>>>(f1w, f1b, f2w, f2b);
    flow_sample_kernel<<<520, 256>>>(x, pos, centers, out);
}

// round 7
// speedup vs baseline: 1.1246x; 1.1246x over previous
#include <cuda_runtime.h>
#include <cstdint>
#include <math.h>

// ---------------- problem constants ----------------
#define BB 8
#define IC1 4
#define OC1 8
#define OC2 10
#define LTOT 131072          // 128*128*8 grid points
#define NUMEL 62720          // 10*28*28*8

// output regions (flat f32 concat: X_t, grid, reg, moved)
#define XT_OFF   0
#define XT_SIZE  (8*4*131072)            // 4194304
#define GRID_OFF XT_SIZE
#define GRID_SIZE (8*131072*3)           // 3145728
#define REG_OFF  (GRID_OFF + GRID_SIZE)  // 7340032
#define MOVED_OFF (REG_OFF + 8)          // 7340040

typedef unsigned long long ull;

// ---------------- scratch (no allocs allowed) ----------------
__device__ float s_h1[8*8*61*488];    // (b,oc,od,oh,w) = 1,905,664 floats
__device__ float s_feat[8*NUMEL];     // conv2 output, reshape layout
__device__ float s_part[32*8*8];      // fc1 partials [o][ks][b]
__device__ float s_RT[8*8*12];        // per (b,t): R row-major [9], T [3]
__device__ int   s_ctr;               // last-block counter (self-resetting)
__device__ float s_xt[8*128*128*8];   // transposed x: [b][d][h][w3c0..3,w4c0..3]

// ---------------- f32x2 helpers ----------------
__device__ __forceinline__ ull ffma2(ull a, ull b, ull c) {
    ull d;
    asm("fma.rn.f32x2 %0, %1, %2, %3;" : "=l"(d) : "l"(a), "l"(b), "l"(c));
    return d;
}
__device__ __forceinline__ ull pack2(float v) {
    ull d;
    asm("mov.b64 %0, {%1, %1};" : "=l"(d) : "f"(v));
    return d;
}
__device__ __forceinline__ float2 unpack2(ull v) {
    float2 r;
    asm("mov.b64 {%0, %1}, %2;" : "=f"(r.x), "=f"(r.y) : "l"(v));
    return r;
}

// =========================================================================
// transpose: x[b,c,d,h,w=3..4] -> s_xt[b,d,h][w2*4+c]  (only w=3,4 needed)
// =========================================================================
__global__ void __launch_bounds__(256)
transpose_kernel(const float* __restrict__ x)
{
    const int idx = blockIdx.x * 256 + threadIdx.x;  // b*16384 + d*128 + h
    const int b = idx >> 14;
    float v[8];
    #pragma unroll
    for (int c = 0; c < 4; c++) {
        const float* p = x + (size_t)(b*4 + c)*131072 + (size_t)(idx & 16383)*8;
        v[c]     = p[3];
        v[4 + c] = p[4];
    }
    float4* dst = (float4*)(s_xt + (size_t)idx * 8);
    dst[0] = make_float4(v[0], v[1], v[2], v[3]);
    dst[1] = make_float4(v[4], v[5], v[6], v[7]);
}

// =========================================================================
// conv1 (7,7,1) + maxpool(2,2,1) + relu   [exact R4 known-good]
// block = (od, b), 256 threads; thread = (oh 0..60) x (wpair 0..3), 244 active
// =========================================================================
__global__ void __launch_bounds__(256, 2)
conv1_kernel(const float* __restrict__ x, const float* __restrict__ wt,
             const float* __restrict__ bias)
{
    __shared__ ull sxu[1024*5];            // [row(1024)][5] ull, row = dd*128+h
    __shared__ ull swu[49*8];              // current ic: [kk*8 + oc] = pack2(w)
    const int od = blockIdx.x, b = blockIdx.y;
    const int tid = threadIdx.x;

    ull acc[OC1][4];
    #pragma unroll
    for (int oc = 0; oc < OC1; oc++)
        #pragma unroll
        for (int p = 0; p < 4; p++) acc[oc][p] = 0ull;

    const int oh = tid >> 2;
    const int wp = tid & 3;
    const bool act = (tid < 244);
    const int hb = 2 * oh;

    for (int ic = 0; ic < IC1; ic++) {
        __syncthreads();
        for (int i = tid; i < 49*8; i += 256) {
            int oc = i / 49, kk = i % 49;
            swu[kk*8 + oc] = pack2(wt[oc*(IC1*49) + ic*49 + kk]);
        }
        const float4* src = (const float4*)(x + ((size_t)(b*IC1 + ic))*131072 + (size_t)od*2048);
        for (int i = tid; i < 2048; i += 256) {
            float4 v = src[i];
            int row = i >> 1;
            int q2  = (i & 1) * 2;
            ull* d = sxu + row*5 + q2;
            d[0] = ((const ull*)&v)[0];
            d[1] = ((const ull*)&v)[1];
        }
        __syncthreads();
        if (act) {
            ull rows[2][8];
            #pragma unroll
            for (int j = 0; j < 8; j++)
                rows[0][j] = sxu[(hb + j)*5 + wp];
            #pragma unroll
            for (int kd = 0; kd < 7; kd++) {
                const int lo = kd & 1, hi = lo ^ 1;
                #pragma unroll
                for (int j = 0; j < 8; j++)
                    rows[hi][j] = sxu[((kd + 1)*128 + hb + j)*5 + wp];
                #pragma unroll
                for (int kh = 0; kh < 7; kh++) {
                    const ulonglong2* wrow = (const ulonglong2*)(swu + (kd*7 + kh)*8);
                    ulonglong2 w0 = wrow[0], w1 = wrow[1], w2 = wrow[2], w3 = wrow[3];
                    #pragma unroll
                    for (int ph = 0; ph < 2; ph++) {
                        ull xl = rows[lo][kh + ph];
                        ull xh = rows[hi][kh + ph];
                        acc[0][ph]   = ffma2(xl, w0.x, acc[0][ph]);
                        acc[0][2+ph] = ffma2(xh, w0.x, acc[0][2+ph]);
                        acc[1][ph]   = ffma2(xl, w0.y, acc[1][ph]);
                        acc[1][2+ph] = ffma2(xh, w0.y, acc[1][2+ph]);
                        acc[2][ph]   = ffma2(xl, w1.x, acc[2][ph]);
                        acc[2][2+ph] = ffma2(xh, w1.x, acc[2][2+ph]);
                        acc[3][ph]   = ffma2(xl, w1.y, acc[3][ph]);
                        acc[3][2+ph] = ffma2(xh, w1.y, acc[3][2+ph]);
                        acc[4][ph]   = ffma2(xl, w2.x, acc[4][ph]);
                        acc[4][2+ph] = ffma2(xh, w2.x, acc[4][2+ph]);
                        acc[5][ph]   = ffma2(xl, w2.y, acc[5][ph]);
                        acc[5][2+ph] = ffma2(xh, w2.y, acc[5][2+ph]);
                        acc[6][ph]   = ffma2(xl, w3.x, acc[6][ph]);
                        acc[6][2+ph] = ffma2(xh, w3.x, acc[6][2+ph]);
                        acc[7][ph]   = ffma2(xl, w3.y, acc[7][ph]);
                        acc[7][2+ph] = ffma2(xh, w3.y, acc[7][2+ph]);
                    }
                }
            }
        }
    }

    if (act) {
        #pragma unroll
        for (int oc = 0; oc < OC1; oc++) {
            float2 v0 = unpack2(acc[oc][0]);
            float2 v1 = unpack2(acc[oc][1]);
            float2 v2 = unpack2(acc[oc][2]);
            float2 v3 = unpack2(acc[oc][3]);
            float bv = bias[oc];
            float mx = fmaxf(fmaxf(fmaxf(v0.x, v1.x), fmaxf(v2.x, v3.x)) + bv, 0.f);
            float my = fmaxf(fmaxf(fmaxf(v0.y, v1.y), fmaxf(v2.y, v3.y)) + bv, 0.f);
            size_t idx = ((size_t)(b*8 + oc)*61 + od)*488 + oh*8 + wp*2;
            *(float2*)(s_h1 + idx) = make_float2(mx, my);
        }
    }
}

// =========================================================================
// conv2 (5,5,1) + maxpool + relu -> s_feat   [exact R4 known-good]
// grid (28 oi, 8 b, 2 ojhalf), 64 threads
// =========================================================================
__global__ void __launch_bounds__(64, 8)
conv2_kernel(const float* __restrict__ wt, const float* __restrict__ bias)
{
    __shared__ ull stu[6*32*5];
    __shared__ ull swu[OC1*25*10];
    const int oi = blockIdx.x, b = blockIdx.y, ojh = blockIdx.z;
    const int tid = threadIdx.x;
    const int h0 = 28 * ojh;

    for (int i = tid; i < OC2*OC1*25; i += 64) {
        int oc = i / (OC1*25);
        int r  = i % (OC1*25);
        int ic = r / 25;
        int kk = r % 25;
        swu[(ic*25 + kk)*10 + oc] = pack2(wt[i]);
    }

    ull acc[OC2][4];
    #pragma unroll
    for (int oc = 0; oc < OC2; oc++)
        #pragma unroll
        for (int p = 0; p < 4; p++) acc[oc][p] = 0ull;

    const int ojr = tid >> 2;
    const int wp  = tid & 3;
    const bool act = (tid < 56);
    const int hbl = 2 * ojr;

    const ull* h1u = (const ull*)s_h1;

    for (int ic = 0; ic < OC1; ic++) {
        __syncthreads();
        const size_t rb = (size_t)(b*8 + ic)*14884;
        for (int j = tid; j < 768; j += 64) {
            int dd = j >> 7;
            int r  = j & 127;
            int hh = r >> 2, q = r & 3;
            stu[(dd*32 + hh)*5 + q] = h1u[rb + (size_t)(2*oi + dd)*244 + (size_t)(h0 + hh)*4 + q];
        }
        __syncthreads();
        if (act) {
            ull rows[2][6];
            #pragma unroll
            for (int j = 0; j < 6; j++)
                rows[0][j] = stu[(hbl + j)*5 + wp];
            #pragma unroll
            for (int kd = 0; kd < 5; kd++) {
                const int lo = kd & 1, hi = lo ^ 1;
                #pragma unroll
                for (int j = 0; j < 6; j++)
                    rows[hi][j] = stu[((kd + 1)*32 + hbl + j)*5 + wp];
                #pragma unroll
                for (int kh = 0; kh < 5; kh++) {
                    const ulonglong2* wrow = (const ulonglong2*)(swu + (ic*25 + kd*5 + kh)*10);
                    ulonglong2 w0 = wrow[0], w1 = wrow[1], w2 = wrow[2], w3 = wrow[3], w4 = wrow[4];
                    #pragma unroll
                    for (int ph = 0; ph < 2; ph++) {
                        ull xl = rows[lo][kh + ph];
                        ull xh = rows[hi][kh + ph];
                        acc[0][ph]   = ffma2(xl, w0.x, acc[0][ph]);
                        acc[0][2+ph] = ffma2(xh, w0.x, acc[0][2+ph]);
                        acc[1][ph]   = ffma2(xl, w0.y, acc[1][ph]);
                        acc[1][2+ph] = ffma2(xh, w0.y, acc[1][2+ph]);
                        acc[2][ph]   = ffma2(xl, w1.x, acc[2][ph]);
                        acc[2][2+ph] = ffma2(xh, w1.x, acc[2][2+ph]);
                        acc[3][ph]   = ffma2(xl, w1.y, acc[3][ph]);
                        acc[3][2+ph] = ffma2(xh, w1.y, acc[3][2+ph]);
                        acc[4][ph]   = ffma2(xl, w2.x, acc[4][ph]);
                        acc[4][2+ph] = ffma2(xh, w2.x, acc[4][2+ph]);
                        acc[5][ph]   = ffma2(xl, w2.y, acc[5][ph]);
                        acc[5][2+ph] = ffma2(xh, w2.y, acc[5][2+ph]);
                        acc[6][ph]   = ffma2(xl, w3.x, acc[6][ph]);
                        acc[6][2+ph] = ffma2(xh, w3.x, acc[6][2+ph]);
                        acc[7][ph]   = ffma2(xl, w3.y, acc[7][ph]);
                        acc[7][2+ph] = ffma2(xh, w3.y, acc[7][2+ph]);
                        acc[8][ph]   = ffma2(xl, w4.x, acc[8][ph]);
                        acc[8][2+ph] = ffma2(xh, w4.x, acc[8][2+ph]);
                        acc[9][ph]   = ffma2(xl, w4.y, acc[9][ph]);
                        acc[9][2+ph] = ffma2(xh, w4.y, acc[9][2+ph]);
                    }
                }
            }
        }
    }

    if (act) {
        const int oj = ojh*14 + ojr;
        #pragma unroll
        for (int oc = 0; oc < OC2; oc++) {
            float2 v0 = unpack2(acc[oc][0]);
            float2 v1 = unpack2(acc[oc][1]);
            float2 v2 = unpack2(acc[oc][2]);
            float2 v3 = unpack2(acc[oc][3]);
            float bv = bias[oc];
            float mx = fmaxf(fmaxf(fmaxf(v0.x, v1.x), fmaxf(v2.x, v3.x)) + bv, 0.f);
            float my = fmaxf(fmaxf(fmaxf(v0.y, v1.y), fmaxf(v2.y, v3.y)) + bv, 0.f);
            size_t idx = (size_t)b*NUMEL + oc*6272 + oi*224 + oj*8 + wp*2;
            *(float2*)(s_feat + idx) = make_float2(mx, my);
        }
    }
}

// =========================================================================
// fc1 partials (float4) + LAST-BLOCK finalize (fc2 + tanh + rigid -> s_RT).
// =========================================================================
__global__ void __launch_bounds__(256)
fc1_kernel(const float* __restrict__ fw, const float* __restrict__ f1b,
           const float* __restrict__ f2w, const float* __restrict__ f2b)
{
    const int o = blockIdx.x, ks = blockIdx.y;
    const int tid = threadIdx.x;
    const int lane = tid & 31, wid = tid >> 5;
    __shared__ float red[8];
    const float4* wrow = (const float4*)(fw + (size_t)o*NUMEL + ks*7840);

    for (int b = 0; b < 8; b++) {
        const float4* frow = (const float4*)(s_feat + (size_t)b*NUMEL + ks*7840);
        float s = 0.f;
        for (int i = tid; i < 1960; i += 256) {
            float4 w = wrow[i], f = frow[i];
            s += w.x*f.x + w.y*f.y + w.z*f.z + w.w*f.w;
        }
        #pragma unroll
        for (int off = 16; off; off >>= 1) s += __shfl_xor_sync(0xffffffffu, s, off);
        if (lane == 0) red[wid] = s;
        __syncthreads();
        if (tid == 0) {
            float t = 0.f;
            #pragma unroll
            for (int w = 0; w < 8; w++) t += red[w];
            s_part[o*64 + ks*8 + b] = t;
        }
        __syncthreads();
    }

    __shared__ int is_last;
    __threadfence();
    if (tid == 0) {
        int v = atomicAdd(&s_ctr, 1);
        is_last = (v == 32*8 - 1);
    }
    __syncthreads();
    if (!is_last) return;
    __threadfence();

    __shared__ float sw[1536];
    __shared__ float sfch[256];
    __shared__ float sth[384];

    for (int i = tid; i < 1536; i += 256) sw[i] = f2w[i];
    {
        const int b = tid >> 5, oo = tid & 31;
        float v = 0.f;
        #pragma unroll
        for (int k = 0; k < 8; k++) v += s_part[oo*64 + k*8 + b];
        sfch[b*32 + oo] = fmaxf(v + f1b[oo], 0.f);
    }
    __syncthreads();

    for (int i = tid; i < 384; i += 256) {
        const int b = i / 48, rr = i % 48;
        float s = f2b[rr];
        const float* w = sw + rr*32;
        const float* f = sfch + b*32;
        #pragma unroll
        for (int j = 0; j < 32; j++) s += f[j] * w[j];
        sth[b*48 + rr] = tanhf(s);
    }
    __syncthreads();

    if (tid < 64) {
        const int b = tid >> 3, t = tid & 7;
        const float* th = sth + b*48 + t*6;
        const float PI = 3.14159274101257324f;
        float c0, s0, c1, s1, c2, s2;
        sincosf(PI*th[0], &s0, &c0);
        sincosf(PI*th[1], &s1, &c1);
        sincosf(PI*th[2], &s2, &c2);
        float R[3][3];
        R[0][0] = c0*c1;  R[0][1] = -s0*c2 + c0*s1*s2;  R[0][2] =  s0*s2 + c0*s1*c2;
        R[1][0] = s0*c1;  R[1][1] =  c0*c2 + s0*s1*s2;  R[1][2] = -c0*s2 + s0*s1*c2;
        R[2][0] = -s1;    R[2][1] =  c1*s2;             R[2][2] =  c1*c2;
        const float szv[3] = {128.f, 128.f, 8.f};
        const float cen[3] = {64.f, 64.f, 4.f};
        float* rr = s_RT + (b*8 + t)*12;
        #pragma unroll
        for (int m = 0; m < 3; m++)
            #pragma unroll
            for (int k = 0; k < 3; k++) rr[m*3 + k] = R[m][k];
        #pragma unroll
        for (int k = 0; k < 3; k++)
            rr[9 + k] = th[3 + k]*szv[k] + cen[k] - (cen[0]*R[0][k] + cen[1]*R[1][k] + cen[2]*R[2][k]);
    }
    if (tid == 0) s_ctr = 0;
}

// =========================================================================
// fused flow + grid write + trilinear grid_sample (via s_xt) + moved/reg
// =========================================================================
__global__ void __launch_bounds__(256)
flow_sample_kernel(const float* __restrict__ pos,
                   const float* __restrict__ centers,
                   float* __restrict__ out)
{
    __shared__ float rt[768];
    const int tid = threadIdx.x;
    for (int i = tid; i < 768; i += 256) rt[i] = s_RT[i];
    __syncthreads();

    const float tess[8][3] = {{32,32,4},{32,96,4},{96,32,4},{96,96,4},
                              {32,64,4},{96,64,4},{64,32,4},{64,96,4}};

    if (blockIdx.x < 512) {
        const int l = blockIdx.x * 256 + tid;
        const int gi = l >> 10, gj = (l >> 3) & 127, gk = l & 7;

        float wn[8], wsum = 0.f;
        #pragma unroll
        for (int t = 0; t < 8; t++) {
            float dx = gi - tess[t][0], dy = gj - tess[t][1], dz = gk - tess[t][2];
            float d = sqrtf(dx*dx + dy*dy + dz*dz);
            float wv = expf(-d * 0.1f);
            wn[t] = wv;
            wsum += wv;
        }
        const float inv = 1.f / wsum;
        const float fi = (float)gi, fj = (float)gj, fk = (float)gk;

        for (int b = 0; b < BB; b++) {
            float a0 = 0.f, a1 = 0.f;
            #pragma unroll
            for (int t = 0; t < 8; t++) {
                const float* r = rt + (b*8 + t)*12;
                float f0 = fi*r[0] + fj*r[3] + fk*r[6] + r[9];
                float f1 = fi*r[1] + fj*r[4] + fk*r[7] + r[10];
                a0 += wn[t]*f0;
                a1 += wn[t]*f1;
            }
            a0 *= inv; a1 *= inv;
            float nf0 = a0 * (1.f/64.f) - 1.f;
            float nf1 = a1 * (1.f/64.f) - 1.f;

            float* g = out + GRID_OFF + ((size_t)b*LTOT + l)*3;
            g[0] = 0.f; g[1] = nf1; g[2] = nf0;

            float iy = (nf1 + 1.f)*64.f - 0.5f;
            float iz = (nf0 + 1.f)*64.f - 0.5f;
            float z0 = floorf(iz), y0 = floorf(iy);
            float acc0 = 0.f, acc1 = 0.f, acc2 = 0.f, acc3 = 0.f;
            #pragma unroll
            for (int dz = 0; dz < 2; dz++) {
                float zc = z0 + dz;
                float wz = 1.f - fabsf(iz - zc);
                bool zv = (zc >= 0.f) && (zc < 128.f);
                int zi = (int)fminf(fmaxf(zc, 0.f), 127.f);
                #pragma unroll
                for (int dy = 0; dy < 2; dy++) {
                    float yc = y0 + dy;
                    float wy = 1.f - fabsf(iy - yc);
                    bool ok = zv && (yc >= 0.f) && (yc < 128.f);
                    int yi = (int)fminf(fmaxf(yc, 0.f), 127.f);
                    float wgt = ok ? wz*wy*0.5f : 0.f;
                    const float4* p = (const float4*)(s_xt + ((size_t)(b*16384 + zi*128 + yi) << 3));
                    float4 lo = p[0], hi = p[1];
                    acc0 += wgt*(lo.x + hi.x);
                    acc1 += wgt*(lo.y + hi.y);
                    acc2 += wgt*(lo.z + hi.z);
                    acc3 += wgt*(lo.w + hi.w);
                }
            }
            out[XT_OFF + (size_t)(b*4 + 0)*LTOT + l] = acc0;
            out[XT_OFF + (size_t)(b*4 + 1)*LTOT + l] = acc1;
            out[XT_OFF + (size_t)(b*4 + 2)*LTOT + l] = acc2;
            out[XT_OFF + (size_t)(b*4 + 3)*LTOT + l] = acc3;
        }
    } else {
        const int b = blockIdx.x - 512;
        __shared__ float red[256];
        float dist = 0.f;
        if (tid < 100) {
            float p0 = pos[(b*100 + tid)*3 + 0];
            float p1 = pos[(b*100 + tid)*3 + 1];
            float p2 = pos[(b*100 + tid)*3 + 2];
            int i0 = (int)fminf(fmaxf(rintf(p0), 0.f), 127.f);
            int i1 = (int)fminf(fmaxf(rintf(p1), 0.f), 127.f);
            int i2 = (int)fminf(fmaxf(rintf(p2), 0.f), 7.f);

            float wn[8], wsum = 0.f;
            #pragma unroll
            for (int t = 0; t < 8; t++) {
                float dx = i0 - tess[t][0], dy = i1 - tess[t][1], dz = i2 - tess[t][2];
                float d = sqrtf(dx*dx + dy*dy + dz*dz);
                float wv = expf(-d * 0.1f);
                wn[t] = wv;
                wsum += wv;
            }
            const float inv = 1.f / wsum;
            const float fi = (float)i0, fj = (float)i1, fk = (float)i2;
            float a0 = 0.f, a1 = 0.f;
            #pragma unroll
            for (int t = 0; t < 8; t++) {
                const float* r = rt + (b*8 + t)*12;
                float f0 = fi*r[0] + fj*r[3] + fk*r[6] + r[9];
                float f1 = fi*r[1] + fj*r[4] + fk*r[7] + r[10];
                a0 += wn[t]*f0;
                a1 += wn[t]*f1;
            }
            a0 *= inv; a1 *= inv;
            float nf0 = a0 * (1.f/64.f) - 1.f;
            float nf1 = a1 * (1.f/64.f) - 1.f;

            float m0 = 2.f*p0 - (0.5f + 0.5f*nf0)*127.f;
            float m1 = 2.f*p1 - (0.5f + 0.5f*nf1)*127.f;
            float m2 = 2.f*p2 - 3.5f;
            float* mo = out + MOVED_OFF + (size_t)(b*100 + tid)*3;
            mo[0] = m0; mo[1] = m1; mo[2] = m2;
            float c0 = centers[tid*3 + 0], c1 = centers[tid*3 + 1], c2 = centers[tid*3 + 2];
            dist = sqrtf((m0-c0)*(m0-c0) + (m1-c1)*(m1-c1) + (m2-c2)*(m2-c2));
        }
        red[tid] = dist;
        __syncthreads();
        for (int k = 128; k > 0; k >>= 1) {
            if (tid < k) red[tid] += red[tid + k];
            __syncthreads();
        }
        if (tid == 0) out[REG_OFF + b] = red[0] / 100.f;
    }
}

// =========================================================================
extern "C" void kernel_launch(void* const* d_in, const int* in_sizes, int n_in,
                              void* d_out, int out_size)
{
    const float* x       = (const float*)d_in[0];
    const float* pos     = (const float*)d_in[1];
    const float* centers = (const float*)d_in[2];
    const float* c1w     = (const float*)d_in[3];
    const float* c1b     = (const float*)d_in[4];
    const float* c2w     = (const float*)d_in[5];
    const float* c2b     = (const float*)d_in[6];
    const float* f1w     = (const float*)d_in[7];
    const float* f1b     = (const float*)d_in[8];
    const float* f2w     = (const float*)d_in[9];
    const float* f2b     = (const float*)d_in[10];
    float* out = (float*)d_out;

    transpose_kernel<<<512, 256>>>(x);
    conv1_kernel<<<dim3(61, 8), 256>>>(x, c1w, c1b);
    conv2_kernel<<<dim3(28, 8, 2), 64>>>(c2w, c2b);
    fc1_kernel<<<dim3(32, 8), 256>>>(f1w, f1b, f2w, f2b);
    flow_sample_kernel<<<520, 256>>>(pos, centers, out);
}

// round 9
// speedup vs baseline: 1.1976x; 1.0650x over previous
#include <cuda_runtime.h>
#include <cstdint>
#include <math.h>

// ---------------- problem constants ----------------
#define BB 8
#define IC1 4
#define OC1 8
#define OC2 10
#define LTOT 131072          // 128*128*8 grid points
#define NUMEL 62720          // 10*28*28*8

// output regions (flat f32 concat: X_t, grid, reg, moved)
#define XT_OFF   0
#define XT_SIZE  (8*4*131072)            // 4194304
#define GRID_OFF XT_SIZE
#define GRID_SIZE (8*131072*3)           // 3145728
#define REG_OFF  (GRID_OFF + GRID_SIZE)  // 7340032
#define MOVED_OFF (REG_OFF + 8)          // 7340040

typedef unsigned long long ull;

// ---------------- scratch (no allocs allowed) ----------------
__device__ float s_h1[8*8*61*488];    // (b,oc,od,oh,w) = 1,905,664 floats
__device__ float s_feat[8*NUMEL];     // conv2 output, reshape layout
__device__ float s_part[32*16*8];     // fc1 partials [o][ks][b]
__device__ float s_RT[8*8*12];        // per (b,t): R row-major [9], T [3]
__device__ int   s_ctr;               // last-block counter (self-resetting)
__device__ float s_xt[8*128*128*8];   // transposed x: [b][d][h][w3c0..3,w4c0..3]

// ---------------- f32x2 helpers ----------------
__device__ __forceinline__ ull ffma2(ull a, ull b, ull c) {
    ull d;
    asm("fma.rn.f32x2 %0, %1, %2, %3;" : "=l"(d) : "l"(a), "l"(b), "l"(c));
    return d;
}
__device__ __forceinline__ ull pack2(float v) {
    ull d;
    asm("mov.b64 %0, {%1, %1};" : "=l"(d) : "f"(v));
    return d;
}
__device__ __forceinline__ float2 unpack2(ull v) {
    float2 r;
    asm("mov.b64 {%0, %1}, %2;" : "=f"(r.x), "=f"(r.y) : "l"(v));
    return r;
}

// =========================================================================
// transpose: x[b,c,d,h,w=3..4] -> s_xt[b,d,h][w2*4+c]  (only w=3,4 needed)
// =========================================================================
__global__ void __launch_bounds__(256)
transpose_kernel(const float* __restrict__ x)
{
    const int idx = blockIdx.x * 256 + threadIdx.x;  // b*16384 + d*128 + h
    const int b = idx >> 14;
    float v[8];
    #pragma unroll
    for (int c = 0; c < 4; c++) {
        const float* p = x + (size_t)(b*4 + c)*131072 + (size_t)(idx & 16383)*8;
        v[c]     = p[3];
        v[4 + c] = p[4];
    }
    float4* dst = (float4*)(s_xt + (size_t)idx * 8);
    dst[0] = make_float4(v[0], v[1], v[2], v[3]);
    dst[1] = make_float4(v[4], v[5], v[6], v[7]);
}

// =========================================================================
// conv1 (7,7,1) + maxpool(2,2,1) + relu
// block = (od, b), 256 threads; thread = (oh 0..60) x (wpair 0..3), 244 active
// NO min-blocks in launch_bounds: uncapped regs -> no inner-loop spills.
// =========================================================================
__global__ void __launch_bounds__(256)
conv1_kernel(const float* __restrict__ x, const float* __restrict__ wt,
             const float* __restrict__ bias)
{
    __shared__ ull sxu[1024*5];            // [row(1024)][5] ull, row = dd*128+h
    __shared__ ull swu[49*8];              // current ic: [kk*8 + oc] = pack2(w)
    const int od = blockIdx.x, b = blockIdx.y;
    const int tid = threadIdx.x;

    ull acc[OC1][4];
    #pragma unroll
    for (int oc = 0; oc < OC1; oc++)
        #pragma unroll
        for (int p = 0; p < 4; p++) acc[oc][p] = 0ull;

    const int oh = tid >> 2;
    const int wp = tid & 3;
    const bool act = (tid < 244);
    const int hb = 2 * oh;

    for (int ic = 0; ic < IC1; ic++) {
        __syncthreads();
        for (int i = tid; i < 49*8; i += 256) {
            int oc = i / 49, kk = i % 49;
            swu[kk*8 + oc] = pack2(wt[oc*(IC1*49) + ic*49 + kk]);
        }
        const float4* src = (const float4*)(x + ((size_t)(b*IC1 + ic))*131072 + (size_t)od*2048);
        for (int i = tid; i < 2048; i += 256) {
            float4 v = src[i];
            int row = i >> 1;
            int q2  = (i & 1) * 2;
            ull* d = sxu + row*5 + q2;
            d[0] = ((const ull*)&v)[0];
            d[1] = ((const ull*)&v)[1];
        }
        __syncthreads();
        if (act) {
            ull rows[2][8];
            #pragma unroll
            for (int j = 0; j < 8; j++)
                rows[0][j] = sxu[(hb + j)*5 + wp];
            #pragma unroll
            for (int kd = 0; kd < 7; kd++) {
                const int lo = kd & 1, hi = lo ^ 1;
                #pragma unroll
                for (int j = 0; j < 8; j++)
                    rows[hi][j] = sxu[((kd + 1)*128 + hb + j)*5 + wp];
                #pragma unroll
                for (int kh = 0; kh < 7; kh++) {
                    const ulonglong2* wrow = (const ulonglong2*)(swu + (kd*7 + kh)*8);
                    ulonglong2 w0 = wrow[0], w1 = wrow[1], w2 = wrow[2], w3 = wrow[3];
                    #pragma unroll
                    for (int ph = 0; ph < 2; ph++) {
                        ull xl = rows[lo][kh + ph];
                        ull xh = rows[hi][kh + ph];
                        acc[0][ph]   = ffma2(xl, w0.x, acc[0][ph]);
                        acc[0][2+ph] = ffma2(xh, w0.x, acc[0][2+ph]);
                        acc[1][ph]   = ffma2(xl, w0.y, acc[1][ph]);
                        acc[1][2+ph] = ffma2(xh, w0.y, acc[1][2+ph]);
                        acc[2][ph]   = ffma2(xl, w1.x, acc[2][ph]);
                        acc[2][2+ph] = ffma2(xh, w1.x, acc[2][2+ph]);
                        acc[3][ph]   = ffma2(xl, w1.y, acc[3][ph]);
                        acc[3][2+ph] = ffma2(xh, w1.y, acc[3][2+ph]);
                        acc[4][ph]   = ffma2(xl, w2.x, acc[4][ph]);
                        acc[4][2+ph] = ffma2(xh, w2.x, acc[4][2+ph]);
                        acc[5][ph]   = ffma2(xl, w2.y, acc[5][ph]);
                        acc[5][2+ph] = ffma2(xh, w2.y, acc[5][2+ph]);
                        acc[6][ph]   = ffma2(xl, w3.x, acc[6][ph]);
                        acc[6][2+ph] = ffma2(xh, w3.x, acc[6][2+ph]);
                        acc[7][ph]   = ffma2(xl, w3.y, acc[7][ph]);
                        acc[7][2+ph] = ffma2(xh, w3.y, acc[7][2+ph]);
                    }
                }
            }
        }
    }

    if (act) {
        #pragma unroll
        for (int oc = 0; oc < OC1; oc++) {
            float2 v0 = unpack2(acc[oc][0]);
            float2 v1 = unpack2(acc[oc][1]);
            float2 v2 = unpack2(acc[oc][2]);
            float2 v3 = unpack2(acc[oc][3]);
            float bv = bias[oc];
            float mx = fmaxf(fmaxf(fmaxf(v0.x, v1.x), fmaxf(v2.x, v3.x)) + bv, 0.f);
            float my = fmaxf(fmaxf(fmaxf(v0.y, v1.y), fmaxf(v2.y, v3.y)) + bv, 0.f);
            size_t idx = ((size_t)(b*8 + oc)*61 + od)*488 + oh*8 + wp*2;
            *(float2*)(s_h1 + idx) = make_float2(mx, my);
        }
    }
}

// =========================================================================
// conv2 (5,5,1) + maxpool + relu -> s_feat
// grid (28 oi, 8 b, 2 ojhalf), 64 threads.  Uncapped regs -> no spills.
// =========================================================================
__global__ void __launch_bounds__(64)
conv2_kernel(const float* __restrict__ wt, const float* __restrict__ bias)
{
    __shared__ ull stu[6*32*5];
    __shared__ ull swu[OC1*25*10];
    const int oi = blockIdx.x, b = blockIdx.y, ojh = blockIdx.z;
    const int tid = threadIdx.x;
    const int h0 = 28 * ojh;

    for (int i = tid; i < OC2*OC1*25; i += 64) {
        int oc = i / (OC1*25);
        int r  = i % (OC1*25);
        int ic = r / 25;
        int kk = r % 25;
        swu[(ic*25 + kk)*10 + oc] = pack2(wt[i]);
    }

    ull acc[OC2][4];
    #pragma unroll
    for (int oc = 0; oc < OC2; oc++)
        #pragma unroll
        for (int p = 0; p < 4; p++) acc[oc][p] = 0ull;

    const int ojr = tid >> 2;
    const int wp  = tid & 3;
    const bool act = (tid < 56);
    const int hbl = 2 * ojr;

    const ull* h1u = (const ull*)s_h1;

    for (int ic = 0; ic < OC1; ic++) {
        __syncthreads();
        const size_t rb = (size_t)(b*8 + ic)*14884;
        for (int j = tid; j < 768; j += 64) {
            int dd = j >> 7;
            int r  = j & 127;
            int hh = r >> 2, q = r & 3;
            stu[(dd*32 + hh)*5 + q] = h1u[rb + (size_t)(2*oi + dd)*244 + (size_t)(h0 + hh)*4 + q];
        }
        __syncthreads();
        if (act) {
            ull rows[2][6];
            #pragma unroll
            for (int j = 0; j < 6; j++)
                rows[0][j] = stu[(hbl + j)*5 + wp];
            #pragma unroll
            for (int kd = 0; kd < 5; kd++) {
                const int lo = kd & 1, hi = lo ^ 1;
                #pragma unroll
                for (int j = 0; j < 6; j++)
                    rows[hi][j] = stu[((kd + 1)*32 + hbl + j)*5 + wp];
                #pragma unroll
                for (int kh = 0; kh < 5; kh++) {
                    const ulonglong2* wrow = (const ulonglong2*)(swu + (ic*25 + kd*5 + kh)*10);
                    ulonglong2 w0 = wrow[0], w1 = wrow[1], w2 = wrow[2], w3 = wrow[3], w4 = wrow[4];
                    #pragma unroll
                    for (int ph = 0; ph < 2; ph++) {
                        ull xl = rows[lo][kh + ph];
                        ull xh = rows[hi][kh + ph];
                        acc[0][ph]   = ffma2(xl, w0.x, acc[0][ph]);
                        acc[0][2+ph] = ffma2(xh, w0.x, acc[0][2+ph]);
                        acc[1][ph]   = ffma2(xl, w0.y, acc[1][ph]);
                        acc[1][2+ph] = ffma2(xh, w0.y, acc[1][2+ph]);
                        acc[2][ph]   = ffma2(xl, w1.x, acc[2][ph]);
                        acc[2][2+ph] = ffma2(xh, w1.x, acc[2][2+ph]);
                        acc[3][ph]   = ffma2(xl, w1.y, acc[3][ph]);
                        acc[3][2+ph] = ffma2(xh, w1.y, acc[3][2+ph]);
                        acc[4][ph]   = ffma2(xl, w2.x, acc[4][ph]);
                        acc[4][2+ph] = ffma2(xh, w2.x, acc[4][2+ph]);
                        acc[5][ph]   = ffma2(xl, w2.y, acc[5][ph]);
                        acc[5][2+ph] = ffma2(xh, w2.y, acc[5][2+ph]);
                        acc[6][ph]   = ffma2(xl, w3.x, acc[6][ph]);
                        acc[6][2+ph] = ffma2(xh, w3.x, acc[6][2+ph]);
                        acc[7][ph]   = ffma2(xl, w3.y, acc[7][ph]);
                        acc[7][2+ph] = ffma2(xh, w3.y, acc[7][2+ph]);
                        acc[8][ph]   = ffma2(xl, w4.x, acc[8][ph]);
                        acc[8][2+ph] = ffma2(xh, w4.x, acc[8][2+ph]);
                        acc[9][ph]   = ffma2(xl, w4.y, acc[9][ph]);
                        acc[9][2+ph] = ffma2(xh, w4.y, acc[9][2+ph]);
                    }
                }
            }
        }
    }

    if (act) {
        const int oj = ojh*14 + ojr;
        #pragma unroll
        for (int oc = 0; oc < OC2; oc++) {
            float2 v0 = unpack2(acc[oc][0]);
            float2 v1 = unpack2(acc[oc][1]);
            float2 v2 = unpack2(acc[oc][2]);
            float2 v3 = unpack2(acc[oc][3]);
            float bv = bias[oc];
            float mx = fmaxf(fmaxf(fmaxf(v0.x, v1.x), fmaxf(v2.x, v3.x)) + bv, 0.f);
            float my = fmaxf(fmaxf(fmaxf(v0.y, v1.y), fmaxf(v2.y, v3.y)) + bv, 0.f);
            size_t idx = (size_t)b*NUMEL + oc*6272 + oi*224 + oj*8 + wp*2;
            *(float2*)(s_feat + idx) = make_float2(mx, my);
        }
    }
}

// =========================================================================
// fc1: batch-parallel partials.  grid (32 o, 16 ks), 256 threads.
// Each thread loads each weight float4 ONCE, dots against all 8 batches.
// LAST-BLOCK finalize: fc2 + tanh + rigid -> s_RT.
// =========================================================================
__global__ void __launch_bounds__(256)
fc1_kernel(const float* __restrict__ fw, const float* __restrict__ f1b,
           const float* __restrict__ f2w, const float* __restrict__ f2b)
{
    const int o = blockIdx.x, ks = blockIdx.y;
    const int tid = threadIdx.x;
    const int lane = tid & 31, wid = tid >> 5;
    __shared__ float red[8][8];        // [warp][batch]
    const float4* wrow = (const float4*)(fw + (size_t)o*NUMEL + ks*3920);

    float acc[8];
    #pragma unroll
    for (int b = 0; b < 8; b++) acc[b] = 0.f;

    for (int i = tid; i < 980; i += 256) {
        float4 w = wrow[i];
        #pragma unroll
        for (int b = 0; b < 8; b++) {
            float4 f = ((const float4*)(s_feat + (size_t)b*NUMEL + ks*3920))[i];
            acc[b] += w.x*f.x + w.y*f.y + w.z*f.z + w.w*f.w;
        }
    }
    #pragma unroll
    for (int b = 0; b < 8; b++) {
        float s = acc[b];
        #pragma unroll
        for (int off = 16; off; off >>= 1) s += __shfl_xor_sync(0xffffffffu, s, off);
        if (lane == 0) red[wid][b] = s;
    }
    __syncthreads();
    if (tid < 8) {
        float t = 0.f;
        #pragma unroll
        for (int w = 0; w < 8; w++) t += red[w][tid];
        s_part[o*128 + ks*8 + tid] = t;
    }

    // ---- last-block finalize ----
    __shared__ int is_last;
    __threadfence();
    if (tid == 0) {
        int v = atomicAdd(&s_ctr, 1);
        is_last = (v == 32*16 - 1);
    }
    __syncthreads();
    if (!is_last) return;
    __threadfence();

    __shared__ float sw[1536];
    __shared__ float sfch[256];
    __shared__ float sth[384];

    for (int i = tid; i < 1536; i += 256) sw[i] = f2w[i];
    {
        const int b = tid >> 5, oo = tid & 31;
        float v = 0.f;
        #pragma unroll
        for (int k = 0; k < 16; k++) v += s_part[oo*128 + k*8 + b];
        sfch[b*32 + oo] = fmaxf(v + f1b[oo], 0.f);
    }
    __syncthreads();

    for (int i = tid; i < 384; i += 256) {
        const int b = i / 48, rr = i % 48;
        float s = f2b[rr];
        const float* w = sw + rr*32;
        const float* f = sfch + b*32;
        #pragma unroll
        for (int j = 0; j < 32; j++) s += f[j] * w[j];
        sth[b*48 + rr] = tanhf(s);
    }
    __syncthreads();

    if (tid < 64) {
        const int b = tid >> 3, t = tid & 7;
        const float* th = sth + b*48 + t*6;
        const float PI = 3.14159274101257324f;
        float c0, s0, c1, s1, c2, s2;
        sincosf(PI*th[0], &s0, &c0);
        sincosf(PI*th[1], &s1, &c1);
        sincosf(PI*th[2], &s2, &c2);
        float R[3][3];
        R[0][0] = c0*c1;  R[0][1] = -s0*c2 + c0*s1*s2;  R[0][2] =  s0*s2 + c0*s1*c2;
        R[1][0] = s0*c1;  R[1][1] =  c0*c2 + s0*s1*s2;  R[1][2] = -c0*s2 + s0*s1*c2;
        R[2][0] = -s1;    R[2][1] =  c1*s2;             R[2][2] =  c1*c2;
        const float szv[3] = {128.f, 128.f, 8.f};
        const float cen[3] = {64.f, 64.f, 4.f};
        float* rr = s_RT + (b*8 + t)*12;
        #pragma unroll
        for (int m = 0; m < 3; m++)
            #pragma unroll
            for (int k = 0; k < 3; k++) rr[m*3 + k] = R[m][k];
        #pragma unroll
        for (int k = 0; k < 3; k++)
            rr[9 + k] = th[3 + k]*szv[k] + cen[k] - (cen[0]*R[0][k] + cen[1]*R[1][k] + cen[2]*R[2][k]);
    }
    if (tid == 0) s_ctr = 0;
}

// =========================================================================
// fused flow + grid write + trilinear grid_sample (via s_xt) + moved/reg
// =========================================================================
__global__ void __launch_bounds__(256)
flow_sample_kernel(const float* __restrict__ pos,
                   const float* __restrict__ centers,
                   float* __restrict__ out)
{
    __shared__ float rt[768];
    const int tid = threadIdx.x;
    for (int i = tid; i < 768; i += 256) rt[i] = s_RT[i];
    __syncthreads();

    const float tess[8][3] = {{32,32,4},{32,96,4},{96,32,4},{96,96,4},
                              {32,64,4},{96,64,4},{64,32,4},{64,96,4}};

    if (blockIdx.x < 512) {
        const int l = blockIdx.x * 256 + tid;
        const int gi = l >> 10, gj = (l >> 3) & 127, gk = l & 7;

        float wn[8], wsum = 0.f;
        #pragma unroll
        for (int t = 0; t < 8; t++) {
            float dx = gi - tess[t][0], dy = gj - tess[t][1], dz = gk - tess[t][2];
            float d = sqrtf(dx*dx + dy*dy + dz*dz);
            float wv = expf(-d * 0.1f);
            wn[t] = wv;
            wsum += wv;
        }
        const float inv = 1.f / wsum;
        const float fi = (float)gi, fj = (float)gj, fk = (float)gk;

        for (int b = 0; b < BB; b++) {
            float a0 = 0.f, a1 = 0.f;
            #pragma unroll
            for (int t = 0; t < 8; t++) {
                const float* r = rt + (b*8 + t)*12;
                float f0 = fi*r[0] + fj*r[3] + fk*r[6] + r[9];
                float f1 = fi*r[1] + fj*r[4] + fk*r[7] + r[10];
                a0 += wn[t]*f0;
                a1 += wn[t]*f1;
            }
            a0 *= inv; a1 *= inv;
            float nf0 = a0 * (1.f/64.f) - 1.f;
            float nf1 = a1 * (1.f/64.f) - 1.f;

            float* g = out + GRID_OFF + ((size_t)b*LTOT + l)*3;
            g[0] = 0.f; g[1] = nf1; g[2] = nf0;

            float iy = (nf1 + 1.f)*64.f - 0.5f;
            float iz = (nf0 + 1.f)*64.f - 0.5f;
            float z0 = floorf(iz), y0 = floorf(iy);
            float acc0 = 0.f, acc1 = 0.f, acc2 = 0.f, acc3 = 0.f;
            #pragma unroll
            for (int dz = 0; dz < 2; dz++) {
                float zc = z0 + dz;
                float wz = 1.f - fabsf(iz - zc);
                bool zv = (zc >= 0.f) && (zc < 128.f);
                int zi = (int)fminf(fmaxf(zc, 0.f), 127.f);
                #pragma unroll
                for (int dy = 0; dy < 2; dy++) {
                    float yc = y0 + dy;
                    float wy = 1.f - fabsf(iy - yc);
                    bool ok = zv && (yc >= 0.f) && (yc < 128.f);
                    int yi = (int)fminf(fmaxf(yc, 0.f), 127.f);
                    float wgt = ok ? wz*wy*0.5f : 0.f;
                    const float4* p = (const float4*)(s_xt + ((size_t)(b*16384 + zi*128 + yi) << 3));
                    float4 lo = p[0], hi = p[1];
                    acc0 += wgt*(lo.x + hi.x);
                    acc1 += wgt*(lo.y + hi.y);
                    acc2 += wgt*(lo.z + hi.z);
                    acc3 += wgt*(lo.w + hi.w);
                }
            }
            out[XT_OFF + (size_t)(b*4 + 0)*LTOT + l] = acc0;
            out[XT_OFF + (size_t)(b*4 + 1)*LTOT + l] = acc1;
            out[XT_OFF + (size_t)(b*4 + 2)*LTOT + l] = acc2;
            out[XT_OFF + (size_t)(b*4 + 3)*LTOT + l] = acc3;
        }
    } else {
        const int b = blockIdx.x - 512;
        __shared__ float red[256];
        float dist = 0.f;
        if (tid < 100) {
            float p0 = pos[(b*100 + tid)*3 + 0];
            float p1 = pos[(b*100 + tid)*3 + 1];
            float p2 = pos[(b*100 + tid)*3 + 2];
            int i0 = (int)fminf(fmaxf(rintf(p0), 0.f), 127.f);
            int i1 = (int)fminf(fmaxf(rintf(p1), 0.f), 127.f);
            int i2 = (int)fminf(fmaxf(rintf(p2), 0.f), 7.f);

            float wn[8], wsum = 0.f;
            #pragma unroll
            for (int t = 0; t < 8; t++) {
                float dx = i0 - tess[t][0], dy = i1 - tess[t][1], dz = i2 - tess[t][2];
                float d = sqrtf(dx*dx + dy*dy + dz*dz);
                float wv = expf(-d * 0.1f);
                wn[t] = wv;
                wsum += wv;
            }
            const float inv = 1.f / wsum;
            const float fi = (float)i0, fj = (float)i1, fk = (float)i2;
            float a0 = 0.f, a1 = 0.f;
            #pragma unroll
            for (int t = 0; t < 8; t++) {
                const float* r = rt + (b*8 + t)*12;
                float f0 = fi*r[0] + fj*r[3] + fk*r[6] + r[9];
                float f1 = fi*r[1] + fj*r[4] + fk*r[7] + r[10];
                a0 += wn[t]*f0;
                a1 += wn[t]*f1;
            }
            a0 *= inv; a1 *= inv;
            float nf0 = a0 * (1.f/64.f) - 1.f;
            float nf1 = a1 * (1.f/64.f) - 1.f;

            float m0 = 2.f*p0 - (0.5f + 0.5f*nf0)*127.f;
            float m1 = 2.f*p1 - (0.5f + 0.5f*nf1)*127.f;
            float m2 = 2.f*p2 - 3.5f;
            float* mo = out + MOVED_OFF + (size_t)(b*100 + tid)*3;
            mo[0] = m0; mo[1] = m1; mo[2] = m2;
            float c0 = centers[tid*3 + 0], c1 = centers[tid*3 + 1], c2 = centers[tid*3 + 2];
            dist = sqrtf((m0-c0)*(m0-c0) + (m1-c1)*(m1-c1) + (m2-c2)*(m2-c2));
        }
        red[tid] = dist;
        __syncthreads();
        for (int k = 128; k > 0; k >>= 1) {
            if (tid < k) red[tid] += red[tid + k];
            __syncthreads();
        }
        if (tid == 0) out[REG_OFF + b] = red[0] / 100.f;
    }
}

// =========================================================================
extern "C" void kernel_launch(void* const* d_in, const int* in_sizes, int n_in,
                              void* d_out, int out_size)
{
    const float* x       = (const float*)d_in[0];
    const float* pos     = (const float*)d_in[1];
    const float* centers = (const float*)d_in[2];
    const float* c1w     = (const float*)d_in[3];
    const float* c1b     = (const float*)d_in[4];
    const float* c2w     = (const float*)d_in[5];
    const float* c2b     = (const float*)d_in[6];
    const float* f1w     = (const float*)d_in[7];
    const float* f1b     = (const float*)d_in[8];
    const float* f2w     = (const float*)d_in[9];
    const float* f2b     = (const float*)d_in[10];
    float* out = (float*)d_out;

    transpose_kernel<<<512, 256>>>(x);
    conv1_kernel<<<dim3(61, 8), 256>>>(x, c1w, c1b);
    conv2_kernel<<<dim3(28, 8, 2), 64>>>(c2w, c2b);
    fc1_kernel<<<dim3(32, 16), 256>>>(f1w, f1b, f2w, f2b);
    flow_sample_kernel<<<520, 256>>>(pos, centers, out);
}